// round 13
// baseline (speedup 1.0000x reference)
#include <cuda_runtime.h>
#include <cuda_fp16.h>

#define NN 100000
#define NE 1280000
#define D 64
#define NBLK ((NN + 1023) / 1024)   // 98 scan blocks
#define NPB 64                       // nodes per block in sage_layer
#define SMS 66                       // sm row stride (even -> 8B-aligned pairs)

// ---- scratch: module-scope device arrays, referenced ONLY inside kernels ----
__device__ int     g_cnt[NN];             // in-degree histogram
__device__ int     g_ptr[NN];             // CSR exclusive offsets
__device__ int     g_pos[NN];             // fill cursors
__device__ int     g_srcl[NE];            // CSR source-node list
__device__ int     g_blk[128];            // scan block sums
__device__ float4  g_h1_4[NN * D / 4];    // layer-1 hidden (fp32, for root path)
__device__ float4  g_h2_4[NN * D / 4];    // fallback h output
__device__ __half2 g_xh[NN * D / 2];      // x in fp16 (gather operand, layer 1)
__device__ __half2 g_h1h[NN * D / 2];     // h1 in fp16 (gather operand, layer 2)
__device__ float4  g_WT4[4 * D * D / 4];  // W1l^T, W1r^T, W2l^T, W2r^T
__device__ int     g_is64;                // edge_index dtype flag

typedef unsigned long long ull;

__device__ __forceinline__ ull pack2(float f) {
    ull r;
    unsigned u = __float_as_uint(f);
    asm("mov.b64 %0, {%1, %1};" : "=l"(r) : "r"(u));
    return r;
}
__device__ __forceinline__ void ffma2(ull& acc, ull a, ull b) {
    asm("fma.rn.f32x2 %0, %1, %2, %0;" : "+l"(acc) : "l"(a), "l"(b));
}
__device__ __forceinline__ void unpack2(ull v, float& lo, float& hi) {
    unsigned a, b;
    asm("mov.b64 {%0, %1}, %2;" : "=r"(a), "=r"(b) : "l"(v));
    lo = __uint_as_float(a);
    hi = __uint_as_float(b);
}

__device__ __forceinline__ int load_idx(const void* ei, int pos, int is64) {
    if (is64) return (int)__ldg((const long long*)ei + pos);
    return __ldg((const int*)ei + pos);
}

// ---------------------------------------------------------------------------
// init: zero g_cnt; convert x -> fp16 (grid-stride); block 0 detects dtype;
// block 1 transposes the 4 weight matrices.
__global__ void init_kernel(const int* __restrict__ ei32,
                            const float* __restrict__ x,
                            const float* __restrict__ W1l, const float* __restrict__ W1r,
                            const float* __restrict__ W2l, const float* __restrict__ W2r) {
    int i = blockIdx.x * 1024 + threadIdx.x;
    if (i < NN) g_cnt[i] = 0;

    // convert x to half2 (grid-stride over NN*D/2 pairs)
    const float2* x2 = (const float2*)x;
    for (int p = i; p < NN * D / 2; p += NBLK * 1024) {
        float2 v = __ldg(&x2[p]);
        g_xh[p] = __floats2half2_rn(v.x, v.y);
    }

    if (blockIdx.x == 0) {
        __shared__ int anyNonZero;
        if (threadIdx.x == 0) anyNonZero = 0;
        __syncthreads();
        if (threadIdx.x < 256) {
            int w = ei32[2 * threadIdx.x + 1];
            for (int k = 0; k < 3; k++) w |= ei32[2 * (threadIdx.x + 256 * (k + 1)) + 1];
            if (w != 0) anyNonZero = 1;
        }
        __syncthreads();
        if (threadIdx.x == 0) g_is64 = anyNonZero ? 0 : 1;
    }

    if (blockIdx.x == 1) {
        const float* src[4] = {W1l, W1r, W2l, W2r};
        float* WT = (float*)g_WT4;
        for (int m = 0; m < 4; m++) {
            const float* S = src[m];
            float* T = WT + m * (D * D);
            for (int i2 = threadIdx.x; i2 < D * D; i2 += 1024) {
                int j = i2 >> 6, k = i2 & 63;
                T[k * D + j] = S[i2];
            }
        }
    }
}

__global__ void hist_kernel(const void* __restrict__ ei) {
    int e = blockIdx.x * blockDim.x + threadIdx.x;
    if (e >= NE) return;
    int d = load_idx(ei, NE + e, g_is64);
    atomicAdd(&g_cnt[d], 1);
}

// block-level exclusive scan of g_cnt -> g_ptr, block totals -> g_blk
__global__ void scan1_kernel() {
    int i = blockIdx.x * 1024 + threadIdx.x;
    int v = (i < NN) ? g_cnt[i] : 0;
    int lane = threadIdx.x & 31, wid = threadIdx.x >> 5;
    int sv = v;
#pragma unroll
    for (int o = 1; o < 32; o <<= 1) {
        int n = __shfl_up_sync(0xffffffffu, sv, o);
        if (lane >= o) sv += n;
    }
    __shared__ int ws[32];
    if (lane == 31) ws[wid] = sv;
    __syncthreads();
    if (wid == 0) {
        int wv = ws[lane];
#pragma unroll
        for (int o = 1; o < 32; o <<= 1) {
            int n = __shfl_up_sync(0xffffffffu, wv, o);
            if (lane >= o) wv += n;
        }
        ws[lane] = wv;
    }
    __syncthreads();
    int off = wid ? ws[wid - 1] : 0;
    int incl = sv + off;
    if (i < NN) g_ptr[i] = incl - v;   // exclusive
    if (threadIdx.x == 1023) g_blk[blockIdx.x] = incl;
}

// exclusive scan of the 98 block sums (single 128-thread block)
__global__ void scan2_kernel() {
    int t = threadIdx.x;
    int v = (t < NBLK) ? g_blk[t] : 0;
    int lane = t & 31, wid = t >> 5;
    int sv = v;
#pragma unroll
    for (int o = 1; o < 32; o <<= 1) {
        int n = __shfl_up_sync(0xffffffffu, sv, o);
        if (lane >= o) sv += n;
    }
    __shared__ int ws[4];
    if (lane == 31) ws[wid] = sv;
    __syncthreads();
    int off = 0;
    for (int w = 0; w < wid; w++) off += ws[w];
    if (t < NBLK) g_blk[t] = sv + off - v;  // exclusive
}

__global__ void scan3_kernel() {
    int i = blockIdx.x * 1024 + threadIdx.x;
    if (i >= NN) return;
    int p = g_ptr[i] + g_blk[blockIdx.x];
    g_ptr[i] = p;
    g_pos[i] = p;
}

__global__ void fill_kernel(const void* __restrict__ ei) {
    int e = blockIdx.x * blockDim.x + threadIdx.x;
    if (e >= NE) return;
    int is64 = g_is64;
    int s = load_idx(ei, e, is64);
    int d = load_idx(ei, NE + e, is64);
    int p = atomicAdd(&g_pos[d], 1);
    g_srcl[p] = s;
}

// ---------------------------------------------------------------------------
// Fused layer: CSR gather-mean (fp16 operands) + relu(mean @ Wl^T + b + feat @ Wr^T)
// 64 nodes/block; 256 threads = 16 channel-groups (q) x 16 slots; each thread
// owns 4 consecutive nodes and 4 channels. Linear phase: packed f32x2 FMA.
template <int LAYER, int HPARAM>
__global__ void __launch_bounds__(256) sage_layer(
                           const float* __restrict__ x,
                           const float* __restrict__ b,
                           float* __restrict__ hout_p,
                           const float* __restrict__ Wh,
                           const float* __restrict__ bh,
                           float* __restrict__ out) {
    __shared__ float smM[D * SMS];   // smM[k*SMS + local_node] : mean
    __shared__ float smX[D * SMS];   // smX[k*SMS + local_node] : root feature
    int t = threadIdx.x;
    int q = t & 15, slot = t >> 4;
    int node0 = blockIdx.x * NPB;
    int s4 = slot * 4;

    const __half2* feath = (LAYER == 0) ? g_xh : g_h1h;   // gather operand (fp16)
    const float*   featf = (LAYER == 0) ? x : (const float*)g_h1_4;  // root (fp32)

    // ---- gather-mean for this thread's 4 nodes, channels 4q..4q+3 ----
#pragma unroll
    for (int i = 0; i < 4; i++) {
        int nl = s4 + i;
        int node = node0 + nl;
        float4 acc = make_float4(0.f, 0.f, 0.f, 0.f);
        float4 xv = make_float4(0.f, 0.f, 0.f, 0.f);
        float rd = 0.f;
        if (node < NN) {
            int beg = __ldg(&g_ptr[node]);
            int cnt = __ldg(&g_cnt[node]);
            int end = beg + cnt;
            int e = beg;
            for (; e + 3 < end; e += 4) {
                int s0 = __ldg(&g_srcl[e + 0]);
                int s1 = __ldg(&g_srcl[e + 1]);
                int s2 = __ldg(&g_srcl[e + 2]);
                int s3 = __ldg(&g_srcl[e + 3]);
                uint2 u0 = __ldg((const uint2*)(feath + (size_t)s0 * (D / 2)) + q);
                uint2 u1 = __ldg((const uint2*)(feath + (size_t)s1 * (D / 2)) + q);
                uint2 u2 = __ldg((const uint2*)(feath + (size_t)s2 * (D / 2)) + q);
                uint2 u3 = __ldg((const uint2*)(feath + (size_t)s3 * (D / 2)) + q);
                float2 a0 = __half22float2(*(__half2*)&u0.x);
                float2 b0 = __half22float2(*(__half2*)&u0.y);
                float2 a1 = __half22float2(*(__half2*)&u1.x);
                float2 b1 = __half22float2(*(__half2*)&u1.y);
                float2 a2 = __half22float2(*(__half2*)&u2.x);
                float2 b2v = __half22float2(*(__half2*)&u2.y);
                float2 a3 = __half22float2(*(__half2*)&u3.x);
                float2 b3 = __half22float2(*(__half2*)&u3.y);
                acc.x += (a0.x + a1.x) + (a2.x + a3.x);
                acc.y += (a0.y + a1.y) + (a2.y + a3.y);
                acc.z += (b0.x + b1.x) + (b2v.x + b3.x);
                acc.w += (b0.y + b1.y) + (b2v.y + b3.y);
            }
            for (; e < end; e++) {
                int s0 = __ldg(&g_srcl[e]);
                uint2 u0 = __ldg((const uint2*)(feath + (size_t)s0 * (D / 2)) + q);
                float2 a0 = __half22float2(*(__half2*)&u0.x);
                float2 b0 = __half22float2(*(__half2*)&u0.y);
                acc.x += a0.x; acc.y += a0.y; acc.z += b0.x; acc.w += b0.y;
            }
            rd = 1.0f / (float)max(cnt, 1);
            xv = __ldg((const float4*)(featf + (size_t)node * D) + q);
        }
        int c = q * 4;
        smM[(c + 0) * SMS + nl] = acc.x * rd;
        smM[(c + 1) * SMS + nl] = acc.y * rd;
        smM[(c + 2) * SMS + nl] = acc.z * rd;
        smM[(c + 3) * SMS + nl] = acc.w * rd;
        smX[(c + 0) * SMS + nl] = xv.x;
        smX[(c + 1) * SMS + nl] = xv.y;
        smX[(c + 2) * SMS + nl] = xv.z;
        smX[(c + 3) * SMS + nl] = xv.w;
    }
    __syncthreads();

    // ---- linear phase: 4 channels x 4 nodes per thread, f32x2 over node pairs
    const float4* wl4 = (const float4*)((const float*)g_WT4 + (2 * LAYER) * (D * D));
    const float4* wr4 = wl4 + (D * D) / 4;
    float4 bb = __ldg((const float4*)b + q);
    ull a0x = pack2(bb.x), a0y = pack2(bb.y), a0z = pack2(bb.z), a0w = pack2(bb.w);
    ull a1x = a0x, a1y = a0y, a1z = a0z, a1w = a0w;

#pragma unroll 4
    for (int k = 0; k < D; k++) {
        float4 wl = __ldg(wl4 + k * 16 + q);
        float4 wr = __ldg(wr4 + k * 16 + q);
        ull wlx = pack2(wl.x), wly = pack2(wl.y), wlz = pack2(wl.z), wlw = pack2(wl.w);
        ull wrx = pack2(wr.x), wry = pack2(wr.y), wrz = pack2(wr.z), wrw = pack2(wr.w);
        ull m0 = *(const ull*)&smM[k * SMS + s4];
        ull m1 = *(const ull*)&smM[k * SMS + s4 + 2];
        ull x0 = *(const ull*)&smX[k * SMS + s4];
        ull x1 = *(const ull*)&smX[k * SMS + s4 + 2];
        ffma2(a0x, wlx, m0); ffma2(a0x, wrx, x0);
        ffma2(a0y, wly, m0); ffma2(a0y, wry, x0);
        ffma2(a0z, wlz, m0); ffma2(a0z, wrz, x0);
        ffma2(a0w, wlw, m0); ffma2(a0w, wrw, x0);
        ffma2(a1x, wlx, m1); ffma2(a1x, wrx, x1);
        ffma2(a1y, wly, m1); ffma2(a1y, wry, x1);
        ffma2(a1z, wlz, m1); ffma2(a1z, wrz, x1);
        ffma2(a1w, wlw, m1); ffma2(a1w, wrw, x1);
    }

    // ---- epilogue: unpack, relu, store h (+fp16 copy), fused head ----
    float o[4][4];  // [node i][channel j]
    unpack2(a0x, o[0][0], o[1][0]); unpack2(a0y, o[0][1], o[1][1]);
    unpack2(a0z, o[0][2], o[1][2]); unpack2(a0w, o[0][3], o[1][3]);
    unpack2(a1x, o[2][0], o[3][0]); unpack2(a1y, o[2][1], o[3][1]);
    unpack2(a1z, o[2][2], o[3][2]); unpack2(a1w, o[2][3], o[3][3]);
#pragma unroll
    for (int i = 0; i < 4; i++)
#pragma unroll
        for (int j = 0; j < 4; j++) o[i][j] = fmaxf(o[i][j], 0.f);

    float* hout;
    if (LAYER == 0)  hout = (float*)g_h1_4;
    else if (HPARAM) hout = hout_p;
    else             hout = (float*)g_h2_4;

#pragma unroll
    for (int i = 0; i < 4; i++) {
        int node = node0 + s4 + i;
        if (node < NN) {
            float4 v = make_float4(o[i][0], o[i][1], o[i][2], o[i][3]);
            ((float4*)(hout + (size_t)node * D))[q] = v;
            if (LAYER == 0) {  // fp16 copy for layer-2 gather
                uint2 u;
                __half2 p0 = __floats2half2_rn(o[i][0], o[i][1]);
                __half2 p1 = __floats2half2_rn(o[i][2], o[i][3]);
                u.x = *(unsigned*)&p0; u.y = *(unsigned*)&p1;
                ((uint2*)(g_h1h + (size_t)node * (D / 2)))[q] = u;
            }
        }
    }

    if (LAYER == 1) {  // head: out[n] = dot(h[n], Wh) + bh, width-16 reduction
        float4 wh = __ldg((const float4*)Wh + q);
        float p[4];
#pragma unroll
        for (int i = 0; i < 4; i++) {
            p[i] = o[i][0] * wh.x + o[i][1] * wh.y + o[i][2] * wh.z + o[i][3] * wh.w;
            p[i] += __shfl_down_sync(0xffffffffu, p[i], 8, 16);
            p[i] += __shfl_down_sync(0xffffffffu, p[i], 4, 16);
            p[i] += __shfl_down_sync(0xffffffffu, p[i], 2, 16);
            p[i] += __shfl_down_sync(0xffffffffu, p[i], 1, 16);
        }
        if (q == 0) {
            float bhv = __ldg(bh);
#pragma unroll
            for (int i = 0; i < 4; i++) {
                int node = node0 + s4 + i;
                if (node < NN) out[node] = p[i] + bhv;
            }
        }
    }
}

// ---------------------------------------------------------------------------
extern "C" void kernel_launch(void* const* d_in, const int* in_sizes, int n_in,
                              void* d_out, int out_size) {
    const float* x   = (const float*)d_in[0];
    const void*  ei  = d_in[1];
    const float* W1l = (const float*)d_in[2];
    const float* W1r = (const float*)d_in[3];
    const float* b1  = (const float*)d_in[4];
    const float* W2l = (const float*)d_in[5];
    const float* W2r = (const float*)d_in[6];
    const float* b2  = (const float*)d_in[7];
    const float* Wh  = (const float*)d_in[8];
    const float* bh  = (const float*)d_in[9];
    float* outp = (float*)d_out;

    const int EG = (NE + 255) / 256;
    const int LG = (NN + NPB - 1) / NPB;

    init_kernel<<<NBLK, 1024>>>((const int*)ei, x, W1l, W1r, W2l, W2r);
    hist_kernel<<<EG, 256>>>(ei);
    scan1_kernel<<<NBLK, 1024>>>();
    scan2_kernel<<<1, 128>>>();
    scan3_kernel<<<NBLK, 1024>>>();
    fill_kernel<<<EG, 256>>>(ei);

    sage_layer<0, 0><<<LG, 256>>>(x, b1, nullptr, nullptr, nullptr, nullptr);
    if (out_size >= NN * (D + 1)) {
        sage_layer<1, 1><<<LG, 256>>>(nullptr, b2, outp + NN, Wh, bh, outp);
    } else {
        sage_layer<1, 0><<<LG, 256>>>(nullptr, b2, nullptr, Wh, bh, outp);
    }
}

// round 14
// speedup vs baseline: 1.2207x; 1.2207x over previous
#include <cuda_runtime.h>

#define NN 100000
#define NE 1280000
#define D 64
#define NBLK ((NN + 1023) / 1024)   // 98 scan blocks
#define NPB 64                       // nodes per block in sage_layer
#define SMS 66                       // sm row stride (even -> 8B-aligned pairs)

// ---- scratch: module-scope device arrays, referenced ONLY inside kernels ----
__device__ int    g_cnt[NN];             // in-degree histogram
__device__ int    g_ptr[NN];             // CSR exclusive offsets
__device__ int    g_pos[NN];             // fill cursors
__device__ int    g_srcl[NE];            // CSR source-node list
__device__ int    g_blk[128];            // scan block sums
__device__ float4 g_h1_4[NN * D / 4];    // layer-1 hidden
__device__ float4 g_h2_4[NN * D / 4];    // fallback h output
__device__ float4 g_WT4[4 * D * D / 4];  // W1l^T, W1r^T, W2l^T, W2r^T
__device__ int    g_is64;                // edge_index dtype flag

typedef unsigned long long ull;

__device__ __forceinline__ ull pack2(float f) {
    ull r;
    unsigned u = __float_as_uint(f);
    asm("mov.b64 %0, {%1, %1};" : "=l"(r) : "r"(u));
    return r;
}
__device__ __forceinline__ void ffma2(ull& acc, ull a, ull b) {
    asm("fma.rn.f32x2 %0, %1, %2, %0;" : "+l"(acc) : "l"(a), "l"(b));
}
__device__ __forceinline__ void unpack2(ull v, float& lo, float& hi) {
    unsigned a, b;
    asm("mov.b64 {%0, %1}, %2;" : "=r"(a), "=r"(b) : "l"(v));
    lo = __uint_as_float(a);
    hi = __uint_as_float(b);
}

__device__ __forceinline__ int load_idx(const void* ei, int pos, int is64) {
    if (is64) return (int)__ldg((const long long*)ei + pos);
    return __ldg((const int*)ei + pos);
}

// ---------------------------------------------------------------------------
// Probe edge_index dtype: int64 data (values < 2^31) has all odd int32 words 0.
__global__ void detect_kernel(const int* __restrict__ ei32) {
    __shared__ int anyNonZero;
    if (threadIdx.x == 0) anyNonZero = 0;
    __syncthreads();
    int w = ei32[2 * threadIdx.x + 1];
    for (int k = 0; k < 3; k++) w |= ei32[2 * (threadIdx.x + 256 * (k + 1)) + 1];
    if (w != 0) anyNonZero = 1;
    __syncthreads();
    if (threadIdx.x == 0) g_is64 = anyNonZero ? 0 : 1;
}

__global__ void zero_cnt_kernel() {
    int i = blockIdx.x * blockDim.x + threadIdx.x;
    if (i < NN) g_cnt[i] = 0;
}

// transpose 4 64x64 weight matrices into g_WT: WT[m][k*64+j] = W[m][j*64+k]
__global__ void transpose_w(const float* __restrict__ W1l, const float* __restrict__ W1r,
                            const float* __restrict__ W2l, const float* __restrict__ W2r) {
    const float* src[4] = {W1l, W1r, W2l, W2r};
    float* WT = (float*)g_WT4;
    int t = threadIdx.x;
    for (int m = 0; m < 4; m++) {
        const float* S = src[m];
        float* T = WT + m * (D * D);
        for (int i = t; i < D * D; i += blockDim.x) {
            int j = i >> 6, k = i & 63;
            T[k * D + j] = S[i];
        }
    }
}

__global__ void hist_kernel(const void* __restrict__ ei) {
    int e = blockIdx.x * blockDim.x + threadIdx.x;
    if (e >= NE) return;
    int d = load_idx(ei, NE + e, g_is64);
    atomicAdd(&g_cnt[d], 1);
}

// block-level exclusive scan of g_cnt -> g_ptr, block totals -> g_blk
__global__ void scan1_kernel() {
    int i = blockIdx.x * 1024 + threadIdx.x;
    int v = (i < NN) ? g_cnt[i] : 0;
    int lane = threadIdx.x & 31, wid = threadIdx.x >> 5;
    int sv = v;
#pragma unroll
    for (int o = 1; o < 32; o <<= 1) {
        int n = __shfl_up_sync(0xffffffffu, sv, o);
        if (lane >= o) sv += n;
    }
    __shared__ int ws[32];
    if (lane == 31) ws[wid] = sv;
    __syncthreads();
    if (wid == 0) {
        int wv = ws[lane];
#pragma unroll
        for (int o = 1; o < 32; o <<= 1) {
            int n = __shfl_up_sync(0xffffffffu, wv, o);
            if (lane >= o) wv += n;
        }
        ws[lane] = wv;
    }
    __syncthreads();
    int off = wid ? ws[wid - 1] : 0;
    int incl = sv + off;
    if (i < NN) g_ptr[i] = incl - v;   // exclusive
    if (threadIdx.x == 1023) g_blk[blockIdx.x] = incl;
}

// exclusive scan of the 98 block sums (single 128-thread block)
__global__ void scan2_kernel() {
    int t = threadIdx.x;
    int v = (t < NBLK) ? g_blk[t] : 0;
    int lane = t & 31, wid = t >> 5;
    int sv = v;
#pragma unroll
    for (int o = 1; o < 32; o <<= 1) {
        int n = __shfl_up_sync(0xffffffffu, sv, o);
        if (lane >= o) sv += n;
    }
    __shared__ int ws[4];
    if (lane == 31) ws[wid] = sv;
    __syncthreads();
    int off = 0;
    for (int w = 0; w < wid; w++) off += ws[w];
    if (t < NBLK) g_blk[t] = sv + off - v;  // exclusive
}

__global__ void scan3_kernel() {
    int i = blockIdx.x * 1024 + threadIdx.x;
    if (i >= NN) return;
    int p = g_ptr[i] + g_blk[blockIdx.x];
    g_ptr[i] = p;
    g_pos[i] = p;
}

__global__ void fill_kernel(const void* __restrict__ ei) {
    int e = blockIdx.x * blockDim.x + threadIdx.x;
    if (e >= NE) return;
    int is64 = g_is64;
    int s = load_idx(ei, e, is64);
    int d = load_idx(ei, NE + e, is64);
    int p = atomicAdd(&g_pos[d], 1);
    g_srcl[p] = s;
}

// ---------------------------------------------------------------------------
// Fused layer: CSR gather-mean + hout = relu(mean @ Wl^T + b + feat @ Wr^T)
// 64 nodes/block, 256 threads.
// GATHER phase: 64 nodes x 4 threads/node; each thread walks its node's edge
//   list once, loading 4 independent float4s (16 channels) per edge.
// LINEAR phase: 16 channel-groups x 16 slots; 4 nodes/thread, packed f32x2 FMA.
template <int LAYER, int HPARAM>
__global__ void __launch_bounds__(256) sage_layer(
                           const float* __restrict__ x,
                           const float* __restrict__ b,
                           float* __restrict__ hout_p,
                           const float* __restrict__ Wh,
                           const float* __restrict__ bh,
                           float* __restrict__ out) {
    __shared__ float smM[D * SMS];   // smM[k*SMS + local_node] : mean
    __shared__ float smX[D * SMS];   // smX[k*SMS + local_node] : root feature
    int t = threadIdx.x;
    int node0 = blockIdx.x * NPB;

    const float* feat = (LAYER == 0) ? x : (const float*)g_h1_4;

    // ---- gather-mean: thread = (node nl, channel-quarter cq) ----
    {
        int nl = t >> 2;          // 0..63
        int cq = t & 3;           // float4 group base: cq*4 .. cq*4+3
        int node = node0 + nl;
        float4 acc[4];
        float4 xv[4];
#pragma unroll
        for (int j = 0; j < 4; j++) {
            acc[j] = make_float4(0.f, 0.f, 0.f, 0.f);
            xv[j] = make_float4(0.f, 0.f, 0.f, 0.f);
        }
        float rd = 0.f;
        if (node < NN) {
            int beg = __ldg(&g_ptr[node]);
            int cnt = __ldg(&g_cnt[node]);
            int end = beg + cnt;
            int e = beg;
            for (; e + 1 < end; e += 2) {
                int s0 = __ldg(&g_srcl[e + 0]);
                int s1 = __ldg(&g_srcl[e + 1]);
                const float4* r0 = (const float4*)(feat + (size_t)s0 * D) + cq * 4;
                const float4* r1 = (const float4*)(feat + (size_t)s1 * D) + cq * 4;
#pragma unroll
                for (int j = 0; j < 4; j++) {
                    float4 v0 = __ldg(r0 + j);
                    float4 v1 = __ldg(r1 + j);
                    acc[j].x += v0.x + v1.x;
                    acc[j].y += v0.y + v1.y;
                    acc[j].z += v0.z + v1.z;
                    acc[j].w += v0.w + v1.w;
                }
            }
            if (e < end) {
                int s0 = __ldg(&g_srcl[e]);
                const float4* r0 = (const float4*)(feat + (size_t)s0 * D) + cq * 4;
#pragma unroll
                for (int j = 0; j < 4; j++) {
                    float4 v0 = __ldg(r0 + j);
                    acc[j].x += v0.x; acc[j].y += v0.y;
                    acc[j].z += v0.z; acc[j].w += v0.w;
                }
            }
            rd = 1.0f / (float)max(cnt, 1);
            const float4* rr = (const float4*)(feat + (size_t)node * D) + cq * 4;
#pragma unroll
            for (int j = 0; j < 4; j++) xv[j] = __ldg(rr + j);
        }
#pragma unroll
        for (int j = 0; j < 4; j++) {
            int c = (cq * 4 + j) * 4;
            smM[(c + 0) * SMS + nl] = acc[j].x * rd;
            smM[(c + 1) * SMS + nl] = acc[j].y * rd;
            smM[(c + 2) * SMS + nl] = acc[j].z * rd;
            smM[(c + 3) * SMS + nl] = acc[j].w * rd;
            smX[(c + 0) * SMS + nl] = xv[j].x;
            smX[(c + 1) * SMS + nl] = xv[j].y;
            smX[(c + 2) * SMS + nl] = xv[j].z;
            smX[(c + 3) * SMS + nl] = xv[j].w;
        }
    }
    __syncthreads();

    // ---- linear phase: 4 channels x 4 nodes per thread, f32x2 over node pairs
    int q = t & 15, slot = t >> 4;
    int s4 = slot * 4;
    const float4* wl4 = (const float4*)((const float*)g_WT4 + (2 * LAYER) * (D * D));
    const float4* wr4 = wl4 + (D * D) / 4;
    float4 bb = __ldg((const float4*)b + q);
    ull a0x = pack2(bb.x), a0y = pack2(bb.y), a0z = pack2(bb.z), a0w = pack2(bb.w);
    ull a1x = a0x, a1y = a0y, a1z = a0z, a1w = a0w;

#pragma unroll 4
    for (int k = 0; k < D; k++) {
        float4 wl = __ldg(wl4 + k * 16 + q);
        float4 wr = __ldg(wr4 + k * 16 + q);
        ull wlx = pack2(wl.x), wly = pack2(wl.y), wlz = pack2(wl.z), wlw = pack2(wl.w);
        ull wrx = pack2(wr.x), wry = pack2(wr.y), wrz = pack2(wr.z), wrw = pack2(wr.w);
        ull m0 = *(const ull*)&smM[k * SMS + s4];
        ull m1 = *(const ull*)&smM[k * SMS + s4 + 2];
        ull x0 = *(const ull*)&smX[k * SMS + s4];
        ull x1 = *(const ull*)&smX[k * SMS + s4 + 2];
        ffma2(a0x, wlx, m0); ffma2(a0x, wrx, x0);
        ffma2(a0y, wly, m0); ffma2(a0y, wry, x0);
        ffma2(a0z, wlz, m0); ffma2(a0z, wrz, x0);
        ffma2(a0w, wlw, m0); ffma2(a0w, wrw, x0);
        ffma2(a1x, wlx, m1); ffma2(a1x, wrx, x1);
        ffma2(a1y, wly, m1); ffma2(a1y, wry, x1);
        ffma2(a1z, wlz, m1); ffma2(a1z, wrz, x1);
        ffma2(a1w, wlw, m1); ffma2(a1w, wrw, x1);
    }

    // ---- epilogue: unpack, relu, store h, fused head ----
    float o[4][4];  // [node i][channel j]
    unpack2(a0x, o[0][0], o[1][0]); unpack2(a0y, o[0][1], o[1][1]);
    unpack2(a0z, o[0][2], o[1][2]); unpack2(a0w, o[0][3], o[1][3]);
    unpack2(a1x, o[2][0], o[3][0]); unpack2(a1y, o[2][1], o[3][1]);
    unpack2(a1z, o[2][2], o[3][2]); unpack2(a1w, o[2][3], o[3][3]);
#pragma unroll
    for (int i = 0; i < 4; i++)
#pragma unroll
        for (int j = 0; j < 4; j++) o[i][j] = fmaxf(o[i][j], 0.f);

    float* hout;
    if (LAYER == 0)  hout = (float*)g_h1_4;
    else if (HPARAM) hout = hout_p;
    else             hout = (float*)g_h2_4;

#pragma unroll
    for (int i = 0; i < 4; i++) {
        int node = node0 + s4 + i;
        if (node < NN) {
            float4 v = make_float4(o[i][0], o[i][1], o[i][2], o[i][3]);
            ((float4*)(hout + (size_t)node * D))[q] = v;
        }
    }

    if (LAYER == 1) {  // head: out[n] = dot(h[n], Wh) + bh, width-16 reduction
        float4 wh = __ldg((const float4*)Wh + q);
        float p[4];
#pragma unroll
        for (int i = 0; i < 4; i++) {
            p[i] = o[i][0] * wh.x + o[i][1] * wh.y + o[i][2] * wh.z + o[i][3] * wh.w;
            p[i] += __shfl_down_sync(0xffffffffu, p[i], 8, 16);
            p[i] += __shfl_down_sync(0xffffffffu, p[i], 4, 16);
            p[i] += __shfl_down_sync(0xffffffffu, p[i], 2, 16);
            p[i] += __shfl_down_sync(0xffffffffu, p[i], 1, 16);
        }
        if (q == 0) {
            float bhv = __ldg(bh);
#pragma unroll
            for (int i = 0; i < 4; i++) {
                int node = node0 + s4 + i;
                if (node < NN) out[node] = p[i] + bhv;
            }
        }
    }
}

// ---------------------------------------------------------------------------
extern "C" void kernel_launch(void* const* d_in, const int* in_sizes, int n_in,
                              void* d_out, int out_size) {
    const float* x   = (const float*)d_in[0];
    const void*  ei  = d_in[1];
    const float* W1l = (const float*)d_in[2];
    const float* W1r = (const float*)d_in[3];
    const float* b1  = (const float*)d_in[4];
    const float* W2l = (const float*)d_in[5];
    const float* W2r = (const float*)d_in[6];
    const float* b2  = (const float*)d_in[7];
    const float* Wh  = (const float*)d_in[8];
    const float* bh  = (const float*)d_in[9];
    float* outp = (float*)d_out;

    const int EG = (NE + 255) / 256;
    const int LG = (NN + NPB - 1) / NPB;

    detect_kernel<<<1, 256>>>((const int*)ei);
    zero_cnt_kernel<<<(NN + 1023) / 1024, 1024>>>();
    transpose_w<<<1, 256>>>(W1l, W1r, W2l, W2r);

    // CSR build (reused by both layers)
    hist_kernel<<<EG, 256>>>(ei);
    scan1_kernel<<<NBLK, 1024>>>();
    scan2_kernel<<<1, 128>>>();
    scan3_kernel<<<NBLK, 1024>>>();
    fill_kernel<<<EG, 256>>>(ei);

    // fused layers
    sage_layer<0, 0><<<LG, 256>>>(x, b1, nullptr, nullptr, nullptr, nullptr);
    if (out_size >= NN * (D + 1)) {
        sage_layer<1, 1><<<LG, 256>>>(nullptr, b2, outp + NN, Wh, bh, outp);
    } else {
        sage_layer<1, 0><<<LG, 256>>>(nullptr, b2, nullptr, Wh, bh, outp);
    }
}

// round 15
// speedup vs baseline: 1.2359x; 1.0124x over previous
#include <cuda_runtime.h>

#define NN 100000
#define NE 1280000
#define D 64
#define NBLK ((NN + 1023) / 1024)   // 98 scan blocks
#define NPB 64                       // nodes per block in sage_layer
#define SMS 66                       // sm row stride (even -> 8B-aligned pairs)

// ---- scratch: module-scope device arrays, referenced ONLY inside kernels ----
__device__ int    g_cnt[NN];             // in-degree histogram
__device__ int    g_ptr[NN];             // CSR exclusive offsets
__device__ int    g_pos[NN];             // fill cursors
__device__ int    g_srcl[NE];            // CSR source-node list
__device__ int    g_blk[128];            // scan block sums
__device__ float4 g_h1_4[NN * D / 4];    // layer-1 hidden
__device__ float4 g_h2_4[NN * D / 4];    // fallback h output
__device__ float4 g_WT4[4 * D * D / 4];  // W1l^T, W1r^T, W2l^T, W2r^T
__device__ int    g_is64;                // edge_index dtype flag

typedef unsigned long long ull;

__device__ __forceinline__ ull pack2(float f) {
    ull r;
    unsigned u = __float_as_uint(f);
    asm("mov.b64 %0, {%1, %1};" : "=l"(r) : "r"(u));
    return r;
}
__device__ __forceinline__ void ffma2(ull& acc, ull a, ull b) {
    asm("fma.rn.f32x2 %0, %1, %2, %0;" : "+l"(acc) : "l"(a), "l"(b));
}
__device__ __forceinline__ void unpack2(ull v, float& lo, float& hi) {
    unsigned a, b;
    asm("mov.b64 {%0, %1}, %2;" : "=r"(a), "=r"(b) : "l"(v));
    lo = __uint_as_float(a);
    hi = __uint_as_float(b);
}

__device__ __forceinline__ int load_idx(const void* ei, int pos, int is64) {
    if (is64) return (int)__ldg((const long long*)ei + pos);
    return __ldg((const int*)ei + pos);
}

// ---------------------------------------------------------------------------
// init: zero g_cnt (all blocks, parallel); block 0 detects edge dtype;
// block 1 transposes the 4 weight matrices. All work is parallel per-block.
__global__ void init_kernel(const int* __restrict__ ei32,
                            const float* __restrict__ W1l, const float* __restrict__ W1r,
                            const float* __restrict__ W2l, const float* __restrict__ W2r) {
    int i = blockIdx.x * 1024 + threadIdx.x;
    if (i < NN) g_cnt[i] = 0;

    if (blockIdx.x == 0) {
        __shared__ int anyNonZero;
        if (threadIdx.x == 0) anyNonZero = 0;
        __syncthreads();
        if (threadIdx.x < 256) {
            // int64 data (values < 2^31) has all odd int32 words 0
            int w = ei32[2 * threadIdx.x + 1];
            for (int k = 0; k < 3; k++) w |= ei32[2 * (threadIdx.x + 256 * (k + 1)) + 1];
            if (w != 0) anyNonZero = 1;
        }
        __syncthreads();
        if (threadIdx.x == 0) g_is64 = anyNonZero ? 0 : 1;
    }

    if (blockIdx.x == 1) {
        const float* src[4] = {W1l, W1r, W2l, W2r};
        float* WT = (float*)g_WT4;
        for (int m = 0; m < 4; m++) {
            const float* S = src[m];
            float* T = WT + m * (D * D);
            for (int i2 = threadIdx.x; i2 < D * D; i2 += 1024) {
                int j = i2 >> 6, k = i2 & 63;
                T[k * D + j] = S[i2];
            }
        }
    }
}

__global__ void hist_kernel(const void* __restrict__ ei) {
    int e = blockIdx.x * blockDim.x + threadIdx.x;
    if (e >= NE) return;
    int d = load_idx(ei, NE + e, g_is64);
    atomicAdd(&g_cnt[d], 1);
}

// block-level exclusive scan of g_cnt -> g_ptr, block totals -> g_blk
__global__ void scan1_kernel() {
    int i = blockIdx.x * 1024 + threadIdx.x;
    int v = (i < NN) ? g_cnt[i] : 0;
    int lane = threadIdx.x & 31, wid = threadIdx.x >> 5;
    int sv = v;
#pragma unroll
    for (int o = 1; o < 32; o <<= 1) {
        int n = __shfl_up_sync(0xffffffffu, sv, o);
        if (lane >= o) sv += n;
    }
    __shared__ int ws[32];
    if (lane == 31) ws[wid] = sv;
    __syncthreads();
    if (wid == 0) {
        int wv = ws[lane];
#pragma unroll
        for (int o = 1; o < 32; o <<= 1) {
            int n = __shfl_up_sync(0xffffffffu, wv, o);
            if (lane >= o) wv += n;
        }
        ws[lane] = wv;
    }
    __syncthreads();
    int off = wid ? ws[wid - 1] : 0;
    int incl = sv + off;
    if (i < NN) g_ptr[i] = incl - v;   // exclusive
    if (threadIdx.x == 1023) g_blk[blockIdx.x] = incl;
}

// fused scan2+scan3: each block redundantly prefix-sums the 98 block totals
// (98 sequential adds, done once per block in shared), then offsets its chunk.
__global__ void scan23_kernel() {
    __shared__ int pre;
    if (threadIdx.x == 0) {
        int s = 0;
        for (int w = 0; w < blockIdx.x; w++) s += g_blk[w];
        pre = s;
    }
    __syncthreads();
    int i = blockIdx.x * 1024 + threadIdx.x;
    if (i >= NN) return;
    int p = g_ptr[i] + pre;
    g_ptr[i] = p;
    g_pos[i] = p;
}

__global__ void fill_kernel(const void* __restrict__ ei) {
    int e = blockIdx.x * blockDim.x + threadIdx.x;
    if (e >= NE) return;
    int is64 = g_is64;
    int s = load_idx(ei, e, is64);
    int d = load_idx(ei, NE + e, is64);
    int p = atomicAdd(&g_pos[d], 1);
    g_srcl[p] = s;
}

// ---------------------------------------------------------------------------
// Fused layer: CSR gather-mean + hout = relu(mean @ Wl^T + b + feat @ Wr^T)
// 64 nodes/block, 256 threads.
// GATHER phase: 64 nodes x 4 threads/node; each thread walks its node's edge
//   list once, loading 4 independent float4s (16 channels) per edge.
// LINEAR phase: 16 channel-groups x 16 slots; 4 nodes/thread, packed f32x2 FMA.
template <int LAYER, int HPARAM>
__global__ void __launch_bounds__(256) sage_layer(
                           const float* __restrict__ x,
                           const float* __restrict__ b,
                           float* __restrict__ hout_p,
                           const float* __restrict__ Wh,
                           const float* __restrict__ bh,
                           float* __restrict__ out) {
    __shared__ float smM[D * SMS];   // smM[k*SMS + local_node] : mean
    __shared__ float smX[D * SMS];   // smX[k*SMS + local_node] : root feature
    int t = threadIdx.x;
    int node0 = blockIdx.x * NPB;

    const float* feat = (LAYER == 0) ? x : (const float*)g_h1_4;

    // ---- gather-mean: thread = (node nl, channel-quarter cq) ----
    {
        int nl = t >> 2;          // 0..63
        int cq = t & 3;           // float4 group base: cq*4 .. cq*4+3
        int node = node0 + nl;
        float4 acc[4];
        float4 xv[4];
#pragma unroll
        for (int j = 0; j < 4; j++) {
            acc[j] = make_float4(0.f, 0.f, 0.f, 0.f);
            xv[j] = make_float4(0.f, 0.f, 0.f, 0.f);
        }
        float rd = 0.f;
        if (node < NN) {
            int beg = __ldg(&g_ptr[node]);
            int cnt = __ldg(&g_cnt[node]);
            int end = beg + cnt;
            int e = beg;
            for (; e + 1 < end; e += 2) {
                int s0 = __ldg(&g_srcl[e + 0]);
                int s1 = __ldg(&g_srcl[e + 1]);
                const float4* r0 = (const float4*)(feat + (size_t)s0 * D) + cq * 4;
                const float4* r1 = (const float4*)(feat + (size_t)s1 * D) + cq * 4;
#pragma unroll
                for (int j = 0; j < 4; j++) {
                    float4 v0 = __ldg(r0 + j);
                    float4 v1 = __ldg(r1 + j);
                    acc[j].x += v0.x + v1.x;
                    acc[j].y += v0.y + v1.y;
                    acc[j].z += v0.z + v1.z;
                    acc[j].w += v0.w + v1.w;
                }
            }
            if (e < end) {
                int s0 = __ldg(&g_srcl[e]);
                const float4* r0 = (const float4*)(feat + (size_t)s0 * D) + cq * 4;
#pragma unroll
                for (int j = 0; j < 4; j++) {
                    float4 v0 = __ldg(r0 + j);
                    acc[j].x += v0.x; acc[j].y += v0.y;
                    acc[j].z += v0.z; acc[j].w += v0.w;
                }
            }
            rd = 1.0f / (float)max(cnt, 1);
            const float4* rr = (const float4*)(feat + (size_t)node * D) + cq * 4;
#pragma unroll
            for (int j = 0; j < 4; j++) xv[j] = __ldg(rr + j);
        }
#pragma unroll
        for (int j = 0; j < 4; j++) {
            int c = (cq * 4 + j) * 4;
            smM[(c + 0) * SMS + nl] = acc[j].x * rd;
            smM[(c + 1) * SMS + nl] = acc[j].y * rd;
            smM[(c + 2) * SMS + nl] = acc[j].z * rd;
            smM[(c + 3) * SMS + nl] = acc[j].w * rd;
            smX[(c + 0) * SMS + nl] = xv[j].x;
            smX[(c + 1) * SMS + nl] = xv[j].y;
            smX[(c + 2) * SMS + nl] = xv[j].z;
            smX[(c + 3) * SMS + nl] = xv[j].w;
        }
    }
    __syncthreads();

    // ---- linear phase: 4 channels x 4 nodes per thread, f32x2 over node pairs
    int q = t & 15, slot = t >> 4;
    int s4 = slot * 4;
    const float4* wl4 = (const float4*)((const float*)g_WT4 + (2 * LAYER) * (D * D));
    const float4* wr4 = wl4 + (D * D) / 4;
    float4 bb = __ldg((const float4*)b + q);
    ull a0x = pack2(bb.x), a0y = pack2(bb.y), a0z = pack2(bb.z), a0w = pack2(bb.w);
    ull a1x = a0x, a1y = a0y, a1z = a0z, a1w = a0w;

#pragma unroll 4
    for (int k = 0; k < D; k++) {
        float4 wl = __ldg(wl4 + k * 16 + q);
        float4 wr = __ldg(wr4 + k * 16 + q);
        ull wlx = pack2(wl.x), wly = pack2(wl.y), wlz = pack2(wl.z), wlw = pack2(wl.w);
        ull wrx = pack2(wr.x), wry = pack2(wr.y), wrz = pack2(wr.z), wrw = pack2(wr.w);
        ull m0 = *(const ull*)&smM[k * SMS + s4];
        ull m1 = *(const ull*)&smM[k * SMS + s4 + 2];
        ull x0 = *(const ull*)&smX[k * SMS + s4];
        ull x1 = *(const ull*)&smX[k * SMS + s4 + 2];
        ffma2(a0x, wlx, m0); ffma2(a0x, wrx, x0);
        ffma2(a0y, wly, m0); ffma2(a0y, wry, x0);
        ffma2(a0z, wlz, m0); ffma2(a0z, wrz, x0);
        ffma2(a0w, wlw, m0); ffma2(a0w, wrw, x0);
        ffma2(a1x, wlx, m1); ffma2(a1x, wrx, x1);
        ffma2(a1y, wly, m1); ffma2(a1y, wry, x1);
        ffma2(a1z, wlz, m1); ffma2(a1z, wrz, x1);
        ffma2(a1w, wlw, m1); ffma2(a1w, wrw, x1);
    }

    // ---- epilogue: unpack, relu, store h, fused head ----
    float o[4][4];  // [node i][channel j]
    unpack2(a0x, o[0][0], o[1][0]); unpack2(a0y, o[0][1], o[1][1]);
    unpack2(a0z, o[0][2], o[1][2]); unpack2(a0w, o[0][3], o[1][3]);
    unpack2(a1x, o[2][0], o[3][0]); unpack2(a1y, o[2][1], o[3][1]);
    unpack2(a1z, o[2][2], o[3][2]); unpack2(a1w, o[2][3], o[3][3]);
#pragma unroll
    for (int i = 0; i < 4; i++)
#pragma unroll
        for (int j = 0; j < 4; j++) o[i][j] = fmaxf(o[i][j], 0.f);

    float* hout;
    if (LAYER == 0)  hout = (float*)g_h1_4;
    else if (HPARAM) hout = hout_p;
    else             hout = (float*)g_h2_4;

#pragma unroll
    for (int i = 0; i < 4; i++) {
        int node = node0 + s4 + i;
        if (node < NN) {
            float4 v = make_float4(o[i][0], o[i][1], o[i][2], o[i][3]);
            ((float4*)(hout + (size_t)node * D))[q] = v;
        }
    }

    if (LAYER == 1) {  // head: out[n] = dot(h[n], Wh) + bh, width-16 reduction
        float4 wh = __ldg((const float4*)Wh + q);
        float p[4];
#pragma unroll
        for (int i = 0; i < 4; i++) {
            p[i] = o[i][0] * wh.x + o[i][1] * wh.y + o[i][2] * wh.z + o[i][3] * wh.w;
            p[i] += __shfl_down_sync(0xffffffffu, p[i], 8, 16);
            p[i] += __shfl_down_sync(0xffffffffu, p[i], 4, 16);
            p[i] += __shfl_down_sync(0xffffffffu, p[i], 2, 16);
            p[i] += __shfl_down_sync(0xffffffffu, p[i], 1, 16);
        }
        if (q == 0) {
            float bhv = __ldg(bh);
#pragma unroll
            for (int i = 0; i < 4; i++) {
                int node = node0 + s4 + i;
                if (node < NN) out[node] = p[i] + bhv;
            }
        }
    }
}

// ---------------------------------------------------------------------------
extern "C" void kernel_launch(void* const* d_in, const int* in_sizes, int n_in,
                              void* d_out, int out_size) {
    const float* x   = (const float*)d_in[0];
    const void*  ei  = d_in[1];
    const float* W1l = (const float*)d_in[2];
    const float* W1r = (const float*)d_in[3];
    const float* b1  = (const float*)d_in[4];
    const float* W2l = (const float*)d_in[5];
    const float* W2r = (const float*)d_in[6];
    const float* b2  = (const float*)d_in[7];
    const float* Wh  = (const float*)d_in[8];
    const float* bh  = (const float*)d_in[9];
    float* outp = (float*)d_out;

    const int EG = (NE + 255) / 256;
    const int LG = (NN + NPB - 1) / NPB;

    // launch order chosen so sage_layer<0> is the 6th launch (ncu -s 5 -c 1)
    init_kernel<<<NBLK, 1024>>>((const int*)ei, W1l, W1r, W2l, W2r);  // 0
    hist_kernel<<<EG, 256>>>(ei);                                      // 1
    scan1_kernel<<<NBLK, 1024>>>();                                    // 2
    scan23_kernel<<<NBLK, 1024>>>();                                   // 3
    fill_kernel<<<EG, 256>>>(ei);                                      // 4

    sage_layer<0, 0><<<LG, 256>>>(x, b1, nullptr, nullptr, nullptr, nullptr);  // 5
    if (out_size >= NN * (D + 1)) {
        sage_layer<1, 1><<<LG, 256>>>(nullptr, b2, outp + NN, Wh, bh, outp);   // 6
    } else {
        sage_layer<1, 0><<<LG, 256>>>(nullptr, b2, nullptr, Wh, bh, outp);
    }
}